// round 2
// baseline (speedup 1.0000x reference)
#include <cuda_runtime.h>
#include <cstdint>

#define THREADS 256
#define ROW_LEN 16384
#define KSEL 64
#define VEC_ITERS (ROW_LEN / 4 / THREADS)  // 16

// Monotonic transform: float bits -> uint32 preserving total order (descending
// float order == descending uint order).
__device__ __forceinline__ uint32_t fwd_xform(uint32_t u) {
    return (u & 0x80000000u) ? ~u : (u | 0x80000000u);
}
__device__ __forceinline__ float inv_xform(uint32_t u) {
    uint32_t b = (u & 0x80000000u) ? (u ^ 0x80000000u) : ~u;
    return __uint_as_float(b);
}

// Warp-aggregated shared-memory histogram add: lanes with the same digit elect
// one leader that adds popc once. Inactive lanes contribute a unique dummy key
// so they form singleton match groups and never touch the histogram.
__device__ __forceinline__ void hist_add(uint32_t* hist, uint32_t digit,
                                         bool active, int lane) {
    uint32_t key = active ? digit : (0x1000u | (uint32_t)lane);
    unsigned m = __match_any_sync(0xFFFFFFFFu, key);
    if (active && lane == (__ffs(m) - 1))
        atomicAdd(&hist[digit], (uint32_t)__popc(m));
}

__global__ void __launch_bounds__(THREADS)
topk64_kernel(const float* __restrict__ x, float* __restrict__ out) {
    extern __shared__ uint32_t sm[];
    uint32_t* data = sm;                 // 16384 words: transformed row
    uint32_t* hist = sm + ROW_LEN;       // 256 words: radix histogram
    uint32_t* sel  = hist + 256;         // 64 words: selected values
    uint32_t* misc = sel + KSEL;         // [0]=cnt, [1]=prefix, [2]=k_rem

    const int row  = blockIdx.x;
    const int tid  = threadIdx.x;
    const int lane = tid & 31;

    if (tid == 0) { misc[0] = 0; misc[1] = 0; misc[2] = KSEL; }
    hist[tid] = 0;
    __syncthreads();

    const uint4* src = reinterpret_cast<const uint4*>(x) + (size_t)row * (ROW_LEN / 4);
    uint4* data4 = reinterpret_cast<uint4*>(data);

    // Single global pass: load, transform, stage to SMEM, MSB-byte histogram.
    #pragma unroll
    for (int it = 0; it < VEC_ITERS; ++it) {
        uint4 v = src[it * THREADS + tid];
        v.x = fwd_xform(v.x); v.y = fwd_xform(v.y);
        v.z = fwd_xform(v.z); v.w = fwd_xform(v.w);
        data4[it * THREADS + tid] = v;
        hist_add(hist, v.x >> 24, true, lane);
        hist_add(hist, v.y >> 24, true, lane);
        hist_add(hist, v.z >> 24, true, lane);
        hist_add(hist, v.w >> 24, true, lane);
    }
    __syncthreads();

    // 4-pass radix select (MSB first) to find exact bit pattern T of the
    // k-th largest element.
    #pragma unroll
    for (int pass = 0; pass < 4; ++pass) {
        const int shift = 24 - 8 * pass;

        // Warp 0: find the selected digit via suffix sums over 256 bins.
        if (tid < 32) {
            uint32_t h[8]; uint32_t t = 0;
            #pragma unroll
            for (int j = 0; j < 8; ++j) { h[j] = hist[tid * 8 + j]; t += h[j]; }
            uint32_t s = t;  // inclusive suffix sum across lanes (bins high->low
                             // means lane 31 holds the top bins)
            #pragma unroll
            for (int off = 1; off < 32; off <<= 1) {
                uint32_t v = __shfl_down_sync(0xFFFFFFFFu, s, off);
                if (tid + off < 32) s += v;
            }
            const uint32_t krem = misc[2];
            uint32_t c = s - t;  // count of elements in bins strictly above
                                 // this lane's top bin
            #pragma unroll
            for (int j = 7; j >= 0; --j) {
                uint32_t nc = c + h[j];
                if (nc >= krem && c < krem) {
                    // unique crossing point: this is the selected digit
                    misc[1] |= (uint32_t)(tid * 8 + j) << shift;
                    misc[2] = krem - c;  // how many ties at this digit to take
                }
                c = nc;
            }
        }
        __syncthreads();
        if (pass == 3) break;

        hist[tid] = 0;
        const uint32_t prefix = misc[1];
        __syncthreads();

        const int nshift = shift - 8;
        const uint32_t mask = ~((1u << shift) - 1u);  // known high bits
        #pragma unroll
        for (int it = 0; it < VEC_ITERS; ++it) {
            uint4 v = data4[it * THREADS + tid];
            #pragma unroll
            for (int j = 0; j < 4; ++j) {
                uint32_t u = (j == 0) ? v.x : (j == 1) ? v.y : (j == 2) ? v.z : v.w;
                bool act = (u & mask) == prefix;
                hist_add(hist, (u >> nshift) & 255u, act, lane);
            }
        }
        __syncthreads();
    }

    const uint32_t T = misc[1];     // exact bit pattern of k-th largest
    const uint32_t krem = misc[2];  // number of copies of T to emit
    (void)krem;

    // Compact strict survivors (> T); there are exactly KSEL - krem <= 63.
    #pragma unroll
    for (int it = 0; it < VEC_ITERS; ++it) {
        uint4 v = data4[it * THREADS + tid];
        #pragma unroll
        for (int j = 0; j < 4; ++j) {
            uint32_t u = (j == 0) ? v.x : (j == 1) ? v.y : (j == 2) ? v.z : v.w;
            if (u > T) {
                uint32_t pos = atomicAdd(&misc[0], 1u);
                sel[pos] = u;
            }
        }
    }
    __syncthreads();
    const uint32_t cgt = misc[0];
    if (tid >= (int)cgt && tid < KSEL) sel[tid] = T;  // tie fill
    __syncthreads();

    // Rank sort the 64 selected values (descending) and write output.
    if (tid < KSEL) {
        uint32_t v = sel[tid];
        int rank = 0;
        #pragma unroll
        for (int j = 0; j < KSEL; ++j) {
            uint32_t u = sel[j];
            rank += (int)((u > v) | ((u == v) & (j < tid)));
        }
        out[(size_t)row * KSEL + rank] = inv_xform(v);
    }
}

extern "C" void kernel_launch(void* const* d_in, const int* in_sizes, int n_in,
                              void* d_out, int out_size) {
    const float* x = (const float*)d_in[0];
    float* out = (float*)d_out;
    int rows = in_sizes[0] / ROW_LEN;  // 32*256 = 8192
    size_t smem = (ROW_LEN + 256 + KSEL + 8) * sizeof(uint32_t);  // ~66.8 KB
    cudaFuncSetAttribute(topk64_kernel,
                         cudaFuncAttributeMaxDynamicSharedMemorySize, (int)smem);
    topk64_kernel<<<rows, THREADS, smem>>>(x, out);
}

// round 3
// speedup vs baseline: 7.0829x; 7.0829x over previous
#include <cuda_runtime.h>
#include <cstdint>

#define THREADS 256
#define ROW_LEN 16384
#define KSEL 64
#define CAP 3072      // candidate buffer capacity (words)
#define KSAMP 12      // target sample count above threshold

// Monotonic transform: float bits -> uint32, descending float order == descending uint order.
__device__ __forceinline__ uint32_t fwd_xform(uint32_t u) {
    return (u & 0x80000000u) ? ~u : (u | 0x80000000u);
}
__device__ __forceinline__ float inv_xform(uint32_t u) {
    return __uint_as_float((u & 0x80000000u) ? (u ^ 0x80000000u) : ~u);
}

// Warp-aggregated histogram add (used only on the small candidate set).
__device__ __forceinline__ void hist_add(uint32_t* hist, uint32_t digit,
                                         bool active, int lane) {
    uint32_t key = active ? digit : (0x1000u | (uint32_t)lane);
    unsigned m = __match_any_sync(0xFFFFFFFFu, key);
    if (active && lane == (__ffs(m) - 1))
        atomicAdd(&hist[digit], (uint32_t)__popc(m));
}

// Warp-aggregated compaction push: one atomic per warp per surviving ballot.
__device__ __forceinline__ void push_cand(uint32_t u, uint32_t T0,
                                          uint32_t* cand, uint32_t* cnt, int lane) {
    bool p = u > T0;
    unsigned m = __ballot_sync(0xFFFFFFFFu, p);
    if (m == 0) return;
    int leader = __ffs(m) - 1;
    uint32_t base = 0;
    if (lane == leader) base = atomicAdd(cnt, (uint32_t)__popc(m));
    base = __shfl_sync(0xFFFFFFFFu, base, leader);
    if (p) {
        uint32_t pos = base + (uint32_t)__popc(m & ((1u << lane) - 1u));
        if (pos < CAP) cand[pos] = u;
    }
}

__global__ void __launch_bounds__(THREADS, 4)
topk64_kernel(const float* __restrict__ x, float* __restrict__ out) {
    __shared__ uint32_t cand[CAP];
    __shared__ uint32_t hist[256];
    __shared__ uint32_t sel[KSEL];
    __shared__ uint32_t misc[4];  // [0]=cand cnt, [1]=radix prefix, [2]=krem, [3]=scratch

    const int row  = blockIdx.x;
    const int tid  = threadIdx.x;
    const int lane = tid & 31;

    const uint32_t* src  = reinterpret_cast<const uint32_t*>(x) + (size_t)row * ROW_LEN;
    const uint4*    src4 = reinterpret_cast<const uint4*>(src);

    // ---- Phase 1: sample threshold T0 (12th largest of first 256 elems) ----
    uint32_t samp = fwd_xform(src[tid]);       // coalesced 1KB, re-hit in L2 below
    if (tid == 0) misc[0] = 0;

    uint32_t T0 = 0;
    #pragma unroll 1
    for (int b = 31; b >= 12; --b) {           // also serves as barrier for misc[0]=0
        uint32_t c = T0 | (1u << b);
        int cnt = __syncthreads_count(samp > c);
        if (cnt >= KSAMP) T0 = c;
    }

    // ---- Phase 2: single global pass, front-batched loads, compact > T0 ----
    #pragma unroll
    for (int ot = 0; ot < 2; ++ot) {
        uint4 v[8];
        #pragma unroll
        for (int j = 0; j < 8; ++j)
            v[j] = src4[(ot * 8 + j) * THREADS + tid];
        #pragma unroll
        for (int j = 0; j < 8; ++j) {
            push_cand(fwd_xform(v[j].x), T0, cand, &misc[0], lane);
            push_cand(fwd_xform(v[j].y), T0, cand, &misc[0], lane);
            push_cand(fwd_xform(v[j].z), T0, cand, &misc[0], lane);
            push_cand(fwd_xform(v[j].w), T0, cand, &misc[0], lane);
        }
    }
    __syncthreads();
    const uint32_t ccnt = misc[0];
    const bool fb = (ccnt < KSEL) || (ccnt > CAP);  // block-uniform

    uint32_t T;  // exact bit pattern of the 64th largest element

    if (!fb) {
        // ---- Phase 3: exact radix-select over <=3072 candidates ----
        hist[tid] = 0;
        if (tid == 0) { misc[1] = 0; misc[2] = KSEL; }
        __syncthreads();

        const int npad = (int)((ccnt + THREADS - 1) / THREADS) * THREADS;
        for (int i = tid; i < npad; i += THREADS) {
            bool in = i < (int)ccnt;
            uint32_t u = in ? cand[i] : 0u;
            hist_add(hist, u >> 24, in, lane);
        }
        __syncthreads();

        #pragma unroll 1
        for (int pass = 0; pass < 4; ++pass) {
            const int shift = 24 - 8 * pass;
            if (tid < 32) {  // warp 0: suffix-scan digit find
                uint32_t h[8]; uint32_t t = 0;
                #pragma unroll
                for (int j = 0; j < 8; ++j) { h[j] = hist[tid * 8 + j]; t += h[j]; }
                uint32_t s = t;
                #pragma unroll
                for (int off = 1; off < 32; off <<= 1) {
                    uint32_t vv = __shfl_down_sync(0xFFFFFFFFu, s, off);
                    if (tid + off < 32) s += vv;
                }
                const uint32_t krem = misc[2];
                uint32_t c = s - t;
                #pragma unroll
                for (int j = 7; j >= 0; --j) {
                    uint32_t nc = c + h[j];
                    if (nc >= krem && c < krem) {
                        misc[1] |= (uint32_t)(tid * 8 + j) << shift;
                        misc[2] = krem - c;
                    }
                    c = nc;
                }
            }
            __syncthreads();
            if (pass == 3) break;

            hist[tid] = 0;
            const uint32_t prefix = misc[1];
            __syncthreads();

            const int nshift = shift - 8;
            const uint32_t mask = ~((1u << shift) - 1u);
            for (int i = tid; i < npad; i += THREADS) {
                bool in = i < (int)ccnt;
                uint32_t u = in ? cand[i] : 0u;
                bool act = in && ((u & mask) == prefix);
                hist_add(hist, (u >> nshift) & 255u, act, lane);
            }
            __syncthreads();
        }
        T = misc[1];

        // compact strict survivors (> T) from candidates; count < 64 guaranteed
        if (tid == 0) misc[3] = 0;
        __syncthreads();
        for (int i = tid; i < (int)ccnt; i += THREADS) {
            uint32_t u = cand[i];
            if (u > T) sel[atomicAdd(&misc[3], 1u)] = u;
        }
    } else {
        // ---- Fallback (rare, exact): bitwise search over the full row ----
        T = 0;
        #pragma unroll 1
        for (int b = 31; b >= 0; --b) {
            uint32_t c = T | (1u << b);
            int loc = 0;
            for (int i = tid; i < ROW_LEN; i += THREADS)
                loc += (int)(fwd_xform(src[i]) >= c);
            int wsum = __reduce_add_sync(0xFFFFFFFFu, loc);
            if (tid == 0) misc[3] = 0;
            __syncthreads();
            if (lane == 0) atomicAdd(&misc[3], (uint32_t)wsum);
            __syncthreads();
            if (misc[3] >= KSEL) T = c;
            __syncthreads();
        }
        if (tid == 0) misc[3] = 0;
        __syncthreads();
        for (int i = tid; i < ROW_LEN; i += THREADS) {
            uint32_t u = fwd_xform(src[i]);
            if (u > T) sel[atomicAdd(&misc[3], 1u)] = u;  // < 64 by construction
        }
    }

    __syncthreads();
    const uint32_t cgt = misc[3];
    if (tid >= (int)cgt && tid < KSEL) sel[tid] = T;  // tie fill
    __syncthreads();

    // ---- Phase 4: rank-sort the 64 winners (descending), write ----
    if (tid < KSEL) {
        uint32_t v = sel[tid];
        int rank = 0;
        #pragma unroll
        for (int j = 0; j < KSEL; ++j) {
            uint32_t u = sel[j];
            rank += (int)((u > v) | ((u == v) & (j < tid)));
        }
        out[(size_t)row * KSEL + rank] = inv_xform(v);
    }
}

extern "C" void kernel_launch(void* const* d_in, const int* in_sizes, int n_in,
                              void* d_out, int out_size) {
    const float* x = (const float*)d_in[0];
    float* out = (float*)d_out;
    int rows = in_sizes[0] / ROW_LEN;  // 8192
    topk64_kernel<<<rows, THREADS>>>(x, out);
}

// round 4
// speedup vs baseline: 12.2977x; 1.7363x over previous
#include <cuda_runtime.h>
#include <cstdint>

#define THREADS 256
#define ROW_LEN 16384
#define KSEL 64
#define NWARP 8
#define SEG 128
#define CAP (NWARP * SEG)   // 1024
#define T0F 2.30f           // fixed filter threshold; exact fallback covers any input

// Monotonic transform: float bits -> uint32, descending float order == descending uint order.
__device__ __forceinline__ uint32_t fwd_xform(uint32_t u) {
    return (u & 0x80000000u) ? ~u : (u | 0x80000000u);
}
__device__ __forceinline__ float inv_xform(uint32_t u) {
    return __uint_as_float((u & 0x80000000u) ? (u ^ 0x80000000u) : ~u);
}

// Warp-aggregated histogram add (small candidate set only).
__device__ __forceinline__ void hist_add(uint32_t* hist, uint32_t digit,
                                         bool active, int lane) {
    uint32_t key = active ? digit : (0x1000u | (uint32_t)lane);
    unsigned m = __match_any_sync(0xFFFFFFFFu, key);
    if (active && lane == (__ffs(m) - 1))
        atomicAdd(&hist[digit], (uint32_t)__popc(m));
}

// Per-lane push into this warp's private segment. Distinct counter per warp ->
// spread-address ATOMS, no ballot/shfl chain.
__device__ __forceinline__ void push(float f, uint32_t* cand, uint32_t* wcnt, int wid) {
    if (f > T0F) {
        uint32_t u = fwd_xform(__float_as_uint(f));
        uint32_t pos = atomicAdd(&wcnt[wid], 1u);
        if (pos < SEG) cand[wid * SEG + pos] = u;
    }
}

__global__ void __launch_bounds__(THREADS, 4)
topk64_kernel(const float* __restrict__ x, float* __restrict__ out) {
    __shared__ uint32_t cand[CAP];
    __shared__ uint32_t hist[256];
    __shared__ uint32_t sel[KSEL];
    __shared__ uint32_t wcnt[NWARP];
    __shared__ uint32_t misc[4];  // [0]=fallback flag, [1]=radix prefix, [2]=krem, [3]=sel cnt

    const int row  = blockIdx.x;
    const int tid  = threadIdx.x;
    const int lane = tid & 31;
    const int wid  = tid >> 5;

    const uint32_t* src  = reinterpret_cast<const uint32_t*>(x) + (size_t)row * ROW_LEN;
    const float4*   src4 = reinterpret_cast<const float4*>(src);

    // Init SMEM: zero-fill candidate buffer (filler = uint 0 = smallest), counters.
    reinterpret_cast<uint4*>(cand)[tid] = make_uint4(0, 0, 0, 0);
    if (tid < NWARP) wcnt[tid] = 0;
    if (tid == 0) { misc[1] = 0; misc[2] = KSEL; misc[3] = 0; }
    hist[tid] = 0;
    __syncthreads();

    // ---- Phase 1: single global pass, front-batched loads, filter f > T0F ----
    #pragma unroll
    for (int ot = 0; ot < 2; ++ot) {
        float4 v[8];
        #pragma unroll
        for (int j = 0; j < 8; ++j)
            v[j] = src4[(ot * 8 + j) * THREADS + tid];
        #pragma unroll
        for (int j = 0; j < 8; ++j) {
            push(v[j].x, cand, wcnt, wid);
            push(v[j].y, cand, wcnt, wid);
            push(v[j].z, cand, wcnt, wid);
            push(v[j].w, cand, wcnt, wid);
        }
    }
    __syncthreads();

    // Fallback check (block-uniform): enough candidates, no segment overflow.
    if (tid == 0) {
        uint32_t total = 0, ovf = 0;
        #pragma unroll
        for (int w = 0; w < NWARP; ++w) {
            total += wcnt[w];
            ovf |= (wcnt[w] > SEG);
        }
        misc[0] = (total < KSEL) || ovf;
    }
    __syncthreads();
    const bool fb = (misc[0] != 0);

    uint32_t T;  // exact bit pattern of the 64th largest element

    if (!fb) {
        // ---- Phase 2: exact radix-select over the 1024-slot buffer ----
        // (filler zeros can never enter top-64: >=64 real candidates have MSB set)
        for (int i = tid; i < CAP; i += THREADS)
            hist_add(hist, cand[i] >> 24, true, lane);
        __syncthreads();

        #pragma unroll 1
        for (int pass = 0; pass < 4; ++pass) {
            const int shift = 24 - 8 * pass;
            if (tid < 32) {  // warp 0: suffix-scan digit find over 256 bins
                uint32_t h[8]; uint32_t t = 0;
                #pragma unroll
                for (int j = 0; j < 8; ++j) { h[j] = hist[tid * 8 + j]; t += h[j]; }
                uint32_t s = t;
                #pragma unroll
                for (int off = 1; off < 32; off <<= 1) {
                    uint32_t vv = __shfl_down_sync(0xFFFFFFFFu, s, off);
                    if (tid + off < 32) s += vv;
                }
                const uint32_t krem = misc[2];
                uint32_t c = s - t;
                #pragma unroll
                for (int j = 7; j >= 0; --j) {
                    uint32_t nc = c + h[j];
                    if (nc >= krem && c < krem) {
                        misc[1] |= (uint32_t)(tid * 8 + j) << shift;
                        misc[2] = krem - c;
                    }
                    c = nc;
                }
            }
            __syncthreads();
            if (pass == 3) break;

            hist[tid] = 0;
            const uint32_t prefix = misc[1];
            __syncthreads();

            const int nshift = shift - 8;
            const uint32_t mask = ~((1u << shift) - 1u);
            for (int i = tid; i < CAP; i += THREADS) {
                uint32_t u = cand[i];
                hist_add(hist, (u >> nshift) & 255u, (u & mask) == prefix, lane);
            }
            __syncthreads();
        }
        T = misc[1];

        // Compact strict survivors (> T); exactly KSEL - krem <= 63 of them.
        for (int i = tid; i < CAP; i += THREADS) {
            uint32_t u = cand[i];
            if (u > T) {
                uint32_t pos = atomicAdd(&misc[3], 1u);
                if (pos < KSEL) sel[pos] = u;
            }
        }
    } else {
        // ---- Fallback (exact, any input): bitwise search over the full row ----
        T = 0;
        #pragma unroll 1
        for (int b = 31; b >= 0; --b) {
            uint32_t c = T | (1u << b);
            int loc = 0;
            for (int i = tid; i < ROW_LEN; i += THREADS)
                loc += (int)(fwd_xform(src[i]) >= c);
            int wsum = __reduce_add_sync(0xFFFFFFFFu, loc);
            if (tid == 0) misc[3] = 0;
            __syncthreads();
            if (lane == 0) atomicAdd(&misc[3], (uint32_t)wsum);
            __syncthreads();
            if (misc[3] >= KSEL) T = c;
            __syncthreads();
        }
        if (tid == 0) misc[3] = 0;
        __syncthreads();
        for (int i = tid; i < ROW_LEN; i += THREADS) {
            uint32_t u = fwd_xform(src[i]);
            if (u > T) {
                uint32_t pos = atomicAdd(&misc[3], 1u);
                if (pos < KSEL) sel[pos] = u;
            }
        }
    }

    __syncthreads();
    const uint32_t cgt = misc[3];
    if (tid >= (int)cgt && tid < KSEL) sel[tid] = T;  // tie fill
    __syncthreads();

    // ---- Phase 3: rank-sort the 64 winners (descending), write ----
    if (tid < KSEL) {
        uint32_t v = sel[tid];
        int rank = 0;
        #pragma unroll
        for (int j = 0; j < KSEL; ++j) {
            uint32_t u = sel[j];
            rank += (int)((u > v) | ((u == v) & (j < tid)));
        }
        out[(size_t)row * KSEL + rank] = inv_xform(v);
    }
}

extern "C" void kernel_launch(void* const* d_in, const int* in_sizes, int n_in,
                              void* d_out, int out_size) {
    const float* x = (const float*)d_in[0];
    float* out = (float*)d_out;
    int rows = in_sizes[0] / ROW_LEN;  // 8192
    topk64_kernel<<<rows, THREADS>>>(x, out);
}